// round 6
// baseline (speedup 1.0000x reference)
#include <cuda_runtime.h>
#include <cstdint>

#define Bb 8
#define Nn 512
#define Ff 128
#define Hh 4
#define Cc 64
#define OUTW (2*Hh*Cc)   // 512

// fp32 scratch: feats [B,H,N,C] + attention logit halves a_s/a_n [B,H,N]
__device__ float g_feats[(size_t)Bb*Hh*Nn*Cc];
__device__ float g_as[(size_t)Bb*Hh*Nn];
__device__ float g_an[(size_t)Bb*Hh*Nn];

// ---------------------------------------------------------------------------
// Kernel 1: feats[b,h,n,c] = sum_f X[b,n,f] * K[h,f,c]
//   + out[b,n, h*64+c] = relu(feats)      (emb half of output)
//   + a_s[b,h,n] = feats[n,:].attn_self ; a_n likewise   (fused epilogue)
// grid (N/64, H, B), 256 threads, 64x64 tile, 4x4 microtile
// ---------------------------------------------------------------------------
__global__ void k1_proj(const float* __restrict__ X,
                        const float* __restrict__ kernels,
                        const float* __restrict__ attn_self,
                        const float* __restrict__ attn_neigh,
                        float* __restrict__ out) {
    extern __shared__ float sm1[];
    float* Ks = sm1;               // 128*64 floats
    float* Xs = sm1 + Ff * Cc;     // 64 rows * 132 (pad) floats

    const int tid = threadIdx.x;
    const int tx = tid & 15;
    const int ty = tid >> 4;
    const int n0 = blockIdx.x * 64;
    const int h  = blockIdx.y;
    const int b  = blockIdx.z;

    // load kernel[h] : 2048 float4
    {
        const float4* src = reinterpret_cast<const float4*>(kernels + (size_t)h * Ff * Cc);
        float4* dst = reinterpret_cast<float4*>(Ks);
        #pragma unroll
        for (int it = 0; it < 8; ++it) dst[tid + it * 256] = src[tid + it * 256];
    }
    // load X tile 64x128 into padded rows (stride 132 floats)
    {
        #pragma unroll
        for (int it = 0; it < 8; ++it) {
            int idx = tid + it * 256;      // float4 index, 2048 total
            int r = idx >> 5, c4 = idx & 31;
            float4 v = reinterpret_cast<const float4*>(
                X + ((size_t)(b * Nn + n0 + r)) * Ff)[c4];
            *reinterpret_cast<float4*>(&Xs[r * 132 + c4 * 4]) = v;
        }
    }
    __syncthreads();

    float acc[4][4];
    #pragma unroll
    for (int i = 0; i < 4; ++i)
        #pragma unroll
        for (int j = 0; j < 4; ++j) acc[i][j] = 0.f;

    const int c0 = tx * 4;
    #pragma unroll 8
    for (int f = 0; f < Ff; ++f) {
        float4 kv = *reinterpret_cast<const float4*>(&Ks[f * Cc + c0]);
        float xa[4];
        #pragma unroll
        for (int i = 0; i < 4; ++i) xa[i] = Xs[(ty + 16 * i) * 132 + f];
        #pragma unroll
        for (int i = 0; i < 4; ++i) {
            acc[i][0] += xa[i] * kv.x;
            acc[i][1] += xa[i] * kv.y;
            acc[i][2] += xa[i] * kv.z;
            acc[i][3] += xa[i] * kv.w;
        }
    }

    const size_t bh = (size_t)b * Hh + h;
    #pragma unroll
    for (int i = 0; i < 4; ++i) {
        int n = n0 + ty + 16 * i;
        float4 v = make_float4(acc[i][0], acc[i][1], acc[i][2], acc[i][3]);
        *reinterpret_cast<float4*>(&g_feats[(bh * Nn + n) * Cc + c0]) = v;
        float4 r = make_float4(fmaxf(v.x, 0.f), fmaxf(v.y, 0.f),
                               fmaxf(v.z, 0.f), fmaxf(v.w, 0.f));
        *reinterpret_cast<float4*>(out + ((size_t)(b * Nn + n)) * OUTW + h * Cc + c0) = r;
    }

    // fused a_s / a_n: each thread dots its 4 columns, 16-lane shfl reduce
    {
        float4 asv = *reinterpret_cast<const float4*>(attn_self  + h * Cc + c0);
        float4 anv = *reinterpret_cast<const float4*>(attn_neigh + h * Cc + c0);
        #pragma unroll
        for (int i = 0; i < 4; ++i) {
            float ps = acc[i][0]*asv.x + acc[i][1]*asv.y + acc[i][2]*asv.z + acc[i][3]*asv.w;
            float pn = acc[i][0]*anv.x + acc[i][1]*anv.y + acc[i][2]*anv.z + acc[i][3]*anv.w;
            #pragma unroll
            for (int o = 8; o; o >>= 1) {
                ps += __shfl_xor_sync(0xffffffffu, ps, o);
                pn += __shfl_xor_sync(0xffffffffu, pn, o);
            }
            if (tx == 0) {
                int n = n0 + ty + 16 * i;
                g_as[bh * Nn + n] = ps;
                g_an[bh * Nn + n] = pn;
            }
        }
    }
}

// ---------------------------------------------------------------------------
// Kernel 2: masked-softmax attention + sparse gather + bias + relu
//   out[b,i, 256 + h*64 + c] = relu( sum_j attn(i,j)*feats[b,h,j,c] + bias[h,c] )
// grid (N/16, H, B) = 1024 blocks, 256 threads (8 warps), warp handles 2 rows.
// Tiny SMEM (a_n only) -> many CTAs/SM. Sparse accumulate gathers feats
// straight from gmem (L1/L2-resident, coalesced 256B/warp), weights broadcast
// via ballot-bit iteration (j = src_lane + 32k, so no index traffic).
// ---------------------------------------------------------------------------
#define ROWS2 16

__global__ void __launch_bounds__(256) k2_attn(
        const float* __restrict__ A,
        const float* __restrict__ biases,
        float* __restrict__ out) {
    __shared__ float a_n_s[Nn];

    const int tid  = threadIdx.x;
    const int lane = tid & 31;
    const int wid  = tid >> 5;
    const int chunk = blockIdx.x, h = blockIdx.y, b = blockIdx.z;
    const size_t bh = (size_t)b * Hh + h;
    const float* feats_g = g_feats + bh * Nn * Cc;

    #pragma unroll
    for (int k = tid; k < Nn; k += 256) a_n_s[k] = g_an[bh * Nn + k];
    __syncthreads();

    float2 bsv = reinterpret_cast<const float2*>(biases + h * Cc)[lane];

    #pragma unroll
    for (int t = 0; t < 2; ++t) {
        const int i = chunk * ROWS2 + wid * 2 + t;
        const float a_si = g_as[bh * Nn + i];
        const float* Arow = A + ((size_t)(b * Nn) + i) * Nn;

        float lv[16];
        unsigned pmask = 0;
        #pragma unroll
        for (int k = 0; k < 16; ++k) {
            float a = __ldcs(Arow + lane + (k << 5));     // streaming: don't evict feats
            float l = a_si + a_n_s[lane + (k << 5)];
            l = l > 0.f ? l : 0.2f * l;                   // LeakyReLU(0.2)
            bool p = (a != 0.f);
            pmask |= (unsigned)p << k;
            lv[k] = p ? l : -1e30f;
        }
        // row max (self-loop guarantees an unmasked entry)
        float m = lv[0];
        #pragma unroll
        for (int k = 1; k < 16; ++k) m = fmaxf(m, lv[k]);
        #pragma unroll
        for (int o = 16; o; o >>= 1) m = fmaxf(m, __shfl_xor_sync(0xffffffffu, m, o));
        // exp only unmasked
        float s = 0.f;
        #pragma unroll
        for (int k = 0; k < 16; ++k) {
            float w = ((pmask >> k) & 1u) ? __expf(lv[k] - m) : 0.f;
            lv[k] = w;
            s += w;
        }
        #pragma unroll
        for (int o = 16; o; o >>= 1) s += __shfl_xor_sync(0xffffffffu, s, o);
        const float inv = 1.f / s;

        // sparse accumulate via ballot-bit iteration (~27 nnz of 512)
        float2 acc = make_float2(0.f, 0.f);
        #pragma unroll
        for (int k = 0; k < 16; ++k) {
            unsigned bal = __ballot_sync(0xffffffffu, (pmask >> k) & 1u);
            const int jbase = k << 5;
            while (bal) {
                int src = __ffs(bal) - 1;
                bal &= bal - 1;
                float w = __shfl_sync(0xffffffffu, lv[k], src);
                float2 f = __ldg(reinterpret_cast<const float2*>(
                               feats_g + (size_t)(jbase + src) * Cc) + lane);
                acc.x += w * f.x;
                acc.y += w * f.y;
            }
        }

        // relu(agg-half) == relu(out_h): maxpool aggregate collapses
        float2 o;
        o.x = fmaxf(acc.x * inv + bsv.x, 0.f);
        o.y = fmaxf(acc.y * inv + bsv.y, 0.f);
        reinterpret_cast<float2*>(
            out + ((size_t)(b * Nn) + i) * OUTW + Hh * Cc + h * Cc)[lane] = o;
    }
}

// ---------------------------------------------------------------------------
extern "C" void kernel_launch(void* const* d_in, const int* in_sizes, int n_in,
                              void* d_out, int out_size) {
    (void)in_sizes; (void)n_in; (void)out_size;
    const float* X          = (const float*)d_in[0];
    const float* A          = (const float*)d_in[1];
    const float* kernels    = (const float*)d_in[2];
    const float* biases     = (const float*)d_in[3];
    const float* attn_self  = (const float*)d_in[4];
    const float* attn_neigh = (const float*)d_in[5];
    float* out = (float*)d_out;

    const int smem1 = (Ff * Cc + 64 * 132) * 4;   // 66560 B
    cudaFuncSetAttribute(k1_proj, cudaFuncAttributeMaxDynamicSharedMemorySize, smem1);

    k1_proj<<<dim3(Nn / 64, Hh, Bb), 256, smem1>>>(X, kernels, attn_self, attn_neigh, out);
    k2_attn<<<dim3(Nn / ROWS2, Hh, Bb), 256>>>(A, biases, out);
}

// round 8
// speedup vs baseline: 1.3044x; 1.3044x over previous
#include <cuda_runtime.h>
#include <cstdint>

#define Bb 8
#define Nn 512
#define Ff 128
#define Hh 4
#define Cc 64
#define OUTW (2*Hh*Cc)   // 512

// fp32 scratch: feats [B,H,N,C] + attention logit halves a_s/a_n [B,H,N]
__device__ float g_feats[(size_t)Bb*Hh*Nn*Cc];
__device__ float g_as[(size_t)Bb*Hh*Nn];
__device__ float g_an[(size_t)Bb*Hh*Nn];

// ---------------------------------------------------------------------------
// Kernel 1: feats[b,h,n,c] = sum_f X[b,n,f] * K[h,f,c]
//   + out[b,n, h*64+c] = relu(feats)      (emb half of output)
//   + a_s[b,h,n], a_n[b,h,n]              (fused attention-logit epilogue)
// grid (N/64, H, B), 256 threads, 64x64 tile, 4x4 microtile
// ---------------------------------------------------------------------------
__global__ void k1_proj(const float* __restrict__ X,
                        const float* __restrict__ kernels,
                        const float* __restrict__ attn_self,
                        const float* __restrict__ attn_neigh,
                        float* __restrict__ out) {
    extern __shared__ float sm1[];
    float* Ks = sm1;               // 128*64 floats
    float* Xs = sm1 + Ff * Cc;     // 64 rows * 132 (pad) floats

    const int tid = threadIdx.x;
    const int tx = tid & 15;
    const int ty = tid >> 4;
    const int n0 = blockIdx.x * 64;
    const int h  = blockIdx.y;
    const int b  = blockIdx.z;

    {
        const float4* src = reinterpret_cast<const float4*>(kernels + (size_t)h * Ff * Cc);
        float4* dst = reinterpret_cast<float4*>(Ks);
        #pragma unroll
        for (int it = 0; it < 8; ++it) dst[tid + it * 256] = src[tid + it * 256];
    }
    {
        #pragma unroll
        for (int it = 0; it < 8; ++it) {
            int idx = tid + it * 256;
            int r = idx >> 5, c4 = idx & 31;
            float4 v = reinterpret_cast<const float4*>(
                X + ((size_t)(b * Nn + n0 + r)) * Ff)[c4];
            *reinterpret_cast<float4*>(&Xs[r * 132 + c4 * 4]) = v;
        }
    }
    __syncthreads();

    float acc[4][4];
    #pragma unroll
    for (int i = 0; i < 4; ++i)
        #pragma unroll
        for (int j = 0; j < 4; ++j) acc[i][j] = 0.f;

    const int c0 = tx * 4;
    #pragma unroll 8
    for (int f = 0; f < Ff; ++f) {
        float4 kv = *reinterpret_cast<const float4*>(&Ks[f * Cc + c0]);
        float xa[4];
        #pragma unroll
        for (int i = 0; i < 4; ++i) xa[i] = Xs[(ty + 16 * i) * 132 + f];
        #pragma unroll
        for (int i = 0; i < 4; ++i) {
            acc[i][0] += xa[i] * kv.x;
            acc[i][1] += xa[i] * kv.y;
            acc[i][2] += xa[i] * kv.z;
            acc[i][3] += xa[i] * kv.w;
        }
    }

    const size_t bh = (size_t)b * Hh + h;
    #pragma unroll
    for (int i = 0; i < 4; ++i) {
        int n = n0 + ty + 16 * i;
        float4 v = make_float4(acc[i][0], acc[i][1], acc[i][2], acc[i][3]);
        *reinterpret_cast<float4*>(&g_feats[(bh * Nn + n) * Cc + c0]) = v;
        float4 r = make_float4(fmaxf(v.x, 0.f), fmaxf(v.y, 0.f),
                               fmaxf(v.z, 0.f), fmaxf(v.w, 0.f));
        *reinterpret_cast<float4*>(out + ((size_t)(b * Nn + n)) * OUTW + h * Cc + c0) = r;
    }

    // fused a_s / a_n epilogue (16-lane shfl reduction over c)
    {
        float4 asv = *reinterpret_cast<const float4*>(attn_self  + h * Cc + c0);
        float4 anv = *reinterpret_cast<const float4*>(attn_neigh + h * Cc + c0);
        #pragma unroll
        for (int i = 0; i < 4; ++i) {
            float ps = acc[i][0]*asv.x + acc[i][1]*asv.y + acc[i][2]*asv.z + acc[i][3]*asv.w;
            float pn = acc[i][0]*anv.x + acc[i][1]*anv.y + acc[i][2]*anv.z + acc[i][3]*anv.w;
            #pragma unroll
            for (int o = 8; o; o >>= 1) {
                ps += __shfl_xor_sync(0xffffffffu, ps, o);
                pn += __shfl_xor_sync(0xffffffffu, pn, o);
            }
            if (tx == 0) {
                int n = n0 + ty + 16 * i;
                g_as[bh * Nn + n] = ps;
                g_an[bh * Nn + n] = pn;
            }
        }
    }
}

// ---------------------------------------------------------------------------
// Kernel 2: one warp = one (b,i) row, ALL 4 heads inside.
//   1) scan A row ONCE -> compact nnz index list (uint16, SMEM)
//   2) per head: logits on compact list only, 2-pass softmax via SMEM wbuf,
//      batched unroll-4 gather of feats from gmem (MLP=4, no shfl chains)
// grid (N/8, B), 256 threads (8 warps).
// ---------------------------------------------------------------------------
#define NW2 8

__global__ void __launch_bounds__(256) k2_attn(
        const float* __restrict__ A,
        const float* __restrict__ biases,
        float* __restrict__ out) {
    __shared__ unsigned short s_idx[NW2][Nn];   // 8 KB
    __shared__ float          s_w[NW2][Nn];     // 16 KB

    const int tid  = threadIdx.x;
    const int lane = tid & 31;
    const int wid  = tid >> 5;
    const int b = blockIdx.y;
    const int i = blockIdx.x * NW2 + wid;

    const unsigned ltmask = (1u << lane) - 1u;
    const float* Arow = A + ((size_t)(b * Nn) + i) * Nn;

    // ---- 1) scan + ballot-compact indices (once for all heads) ----
    int count = 0;
    #pragma unroll
    for (int k = 0; k < 16; ++k) {
        const int j = lane + (k << 5);
        bool p = (__ldcs(Arow + j) != 0.f);
        unsigned bal = __ballot_sync(0xffffffffu, p);
        if (p) s_idx[wid][count + __popc(bal & ltmask)] = (unsigned short)j;
        count += __popc(bal);
    }
    __syncwarp();

    // ---- 2) per-head masked softmax + sparse gather ----
    #pragma unroll
    for (int h = 0; h < Hh; ++h) {
        const size_t bh = (size_t)b * Hh + h;
        const float* an_h = g_an + bh * Nn;
        const float* feats_h = g_feats + bh * Nn * Cc;
        const float a_si = __ldg(g_as + bh * Nn + i);

        // pass 1: logits -> smem, track max
        float m = -1e30f;
        for (int e = lane; e < count; e += 32) {
            float l = a_si + __ldg(an_h + s_idx[wid][e]);
            l = l > 0.f ? l : 0.2f * l;            // LeakyReLU(0.2)
            s_w[wid][e] = l;
            m = fmaxf(m, l);
        }
        #pragma unroll
        for (int o = 16; o; o >>= 1) m = fmaxf(m, __shfl_xor_sync(0xffffffffu, m, o));
        __syncwarp();

        // pass 2: exp + sum
        float s = 0.f;
        for (int e = lane; e < count; e += 32) {
            float w = __expf(s_w[wid][e] - m);
            s_w[wid][e] = w;
            s += w;
        }
        #pragma unroll
        for (int o = 16; o; o >>= 1) s += __shfl_xor_sync(0xffffffffu, s, o);
        const float inv = 1.f / s;
        __syncwarp();

        // batched sparse accumulate (independent loads -> MLP=4)
        float2 acc = make_float2(0.f, 0.f);
        int e = 0;
        for (; e + 4 <= count; e += 4) {
            int j0 = s_idx[wid][e+0], j1 = s_idx[wid][e+1];
            int j2 = s_idx[wid][e+2], j3 = s_idx[wid][e+3];
            float w0 = s_w[wid][e+0], w1 = s_w[wid][e+1];
            float w2 = s_w[wid][e+2], w3 = s_w[wid][e+3];
            float2 f0 = __ldg(reinterpret_cast<const float2*>(feats_h + (size_t)j0 * Cc) + lane);
            float2 f1 = __ldg(reinterpret_cast<const float2*>(feats_h + (size_t)j1 * Cc) + lane);
            float2 f2 = __ldg(reinterpret_cast<const float2*>(feats_h + (size_t)j2 * Cc) + lane);
            float2 f3 = __ldg(reinterpret_cast<const float2*>(feats_h + (size_t)j3 * Cc) + lane);
            acc.x += w0 * f0.x; acc.y += w0 * f0.y;
            acc.x += w1 * f1.x; acc.y += w1 * f1.y;
            acc.x += w2 * f2.x; acc.y += w2 * f2.y;
            acc.x += w3 * f3.x; acc.y += w3 * f3.y;
        }
        for (; e < count; ++e) {
            int jj = s_idx[wid][e];
            float ww = s_w[wid][e];
            float2 f = __ldg(reinterpret_cast<const float2*>(feats_h + (size_t)jj * Cc) + lane);
            acc.x += ww * f.x; acc.y += ww * f.y;
        }
        __syncwarp();   // buffer reused by next head

        // relu(agg-half) == relu(out_h): maxpool aggregate collapses
        float2 bsv = reinterpret_cast<const float2*>(biases + h * Cc)[lane];
        float2 o;
        o.x = fmaxf(acc.x * inv + bsv.x, 0.f);
        o.y = fmaxf(acc.y * inv + bsv.y, 0.f);
        reinterpret_cast<float2*>(
            out + ((size_t)(b * Nn) + i) * OUTW + Hh * Cc + h * Cc)[lane] = o;
    }
}

// ---------------------------------------------------------------------------
extern "C" void kernel_launch(void* const* d_in, const int* in_sizes, int n_in,
                              void* d_out, int out_size) {
    (void)in_sizes; (void)n_in; (void)out_size;
    const float* X          = (const float*)d_in[0];
    const float* A          = (const float*)d_in[1];
    const float* kernels    = (const float*)d_in[2];
    const float* biases     = (const float*)d_in[3];
    const float* attn_self  = (const float*)d_in[4];
    const float* attn_neigh = (const float*)d_in[5];
    float* out = (float*)d_out;

    const int smem1 = (Ff * Cc + 64 * 132) * 4;   // 66560 B
    cudaFuncSetAttribute(k1_proj, cudaFuncAttributeMaxDynamicSharedMemorySize, smem1);

    k1_proj<<<dim3(Nn / 64, Hh, Bb), 256, smem1>>>(X, kernels, attn_self, attn_neigh, out);
    k2_attn<<<dim3(Nn / NW2, Bb), 256>>>(A, biases, out);
}

// round 10
// speedup vs baseline: 1.5055x; 1.1542x over previous
#include <cuda_runtime.h>
#include <cstdint>

#define Bb 8
#define Nn 512
#define Ff 128
#define Hh 4
#define Cc 64
#define OUTW (2*Hh*Cc)   // 512

// fp32 scratch: feats [B,H,N,C] + attention logit halves a_s/a_n [B,H,N]
__device__ float g_feats[(size_t)Bb*Hh*Nn*Cc];
__device__ float g_as[(size_t)Bb*Hh*Nn];
__device__ float g_an[(size_t)Bb*Hh*Nn];

// ---------------------------------------------------------------------------
// Kernel 1: feats[b,h,n,c] = sum_f X[b,n,f] * K[h,f,c]
//   + out[b,n, h*64+c] = relu(feats)      (emb half)
//   + a_s[b,h,n], a_n[b,h,n]              (fused logit epilogue)
// grid (N/64, H, B), 256 threads, 64x64 tile, 4x4 microtile  (at FFMA floor)
// ---------------------------------------------------------------------------
__global__ void k1_proj(const float* __restrict__ X,
                        const float* __restrict__ kernels,
                        const float* __restrict__ attn_self,
                        const float* __restrict__ attn_neigh,
                        float* __restrict__ out) {
    extern __shared__ float sm1[];
    float* Ks = sm1;               // 128*64 floats
    float* Xs = sm1 + Ff * Cc;     // 64 rows * 132 (pad) floats

    const int tid = threadIdx.x;
    const int tx = tid & 15;
    const int ty = tid >> 4;
    const int n0 = blockIdx.x * 64;
    const int h  = blockIdx.y;
    const int b  = blockIdx.z;

    {
        const float4* src = reinterpret_cast<const float4*>(kernels + (size_t)h * Ff * Cc);
        float4* dst = reinterpret_cast<float4*>(Ks);
        #pragma unroll
        for (int it = 0; it < 8; ++it) dst[tid + it * 256] = src[tid + it * 256];
    }
    {
        #pragma unroll
        for (int it = 0; it < 8; ++it) {
            int idx = tid + it * 256;
            int r = idx >> 5, c4 = idx & 31;
            float4 v = reinterpret_cast<const float4*>(
                X + ((size_t)(b * Nn + n0 + r)) * Ff)[c4];
            *reinterpret_cast<float4*>(&Xs[r * 132 + c4 * 4]) = v;
        }
    }
    __syncthreads();

    float acc[4][4];
    #pragma unroll
    for (int i = 0; i < 4; ++i)
        #pragma unroll
        for (int j = 0; j < 4; ++j) acc[i][j] = 0.f;

    const int c0 = tx * 4;
    #pragma unroll 8
    for (int f = 0; f < Ff; ++f) {
        float4 kv = *reinterpret_cast<const float4*>(&Ks[f * Cc + c0]);
        float xa[4];
        #pragma unroll
        for (int i = 0; i < 4; ++i) xa[i] = Xs[(ty + 16 * i) * 132 + f];
        #pragma unroll
        for (int i = 0; i < 4; ++i) {
            acc[i][0] += xa[i] * kv.x;
            acc[i][1] += xa[i] * kv.y;
            acc[i][2] += xa[i] * kv.z;
            acc[i][3] += xa[i] * kv.w;
        }
    }

    const size_t bh = (size_t)b * Hh + h;
    #pragma unroll
    for (int i = 0; i < 4; ++i) {
        int n = n0 + ty + 16 * i;
        float4 v = make_float4(acc[i][0], acc[i][1], acc[i][2], acc[i][3]);
        *reinterpret_cast<float4*>(&g_feats[(bh * Nn + n) * Cc + c0]) = v;
        float4 r = make_float4(fmaxf(v.x, 0.f), fmaxf(v.y, 0.f),
                               fmaxf(v.z, 0.f), fmaxf(v.w, 0.f));
        *reinterpret_cast<float4*>(out + ((size_t)(b * Nn + n)) * OUTW + h * Cc + c0) = r;
    }

    {
        float4 asv = *reinterpret_cast<const float4*>(attn_self  + h * Cc + c0);
        float4 anv = *reinterpret_cast<const float4*>(attn_neigh + h * Cc + c0);
        #pragma unroll
        for (int i = 0; i < 4; ++i) {
            float ps = acc[i][0]*asv.x + acc[i][1]*asv.y + acc[i][2]*asv.z + acc[i][3]*asv.w;
            float pn = acc[i][0]*anv.x + acc[i][1]*anv.y + acc[i][2]*anv.z + acc[i][3]*anv.w;
            #pragma unroll
            for (int o = 8; o; o >>= 1) {
                ps += __shfl_xor_sync(0xffffffffu, ps, o);
                pn += __shfl_xor_sync(0xffffffffu, pn, o);
            }
            if (tx == 0) {
                int n = n0 + ty + 16 * i;
                g_as[bh * Nn + n] = ps;
                g_an[bh * Nn + n] = pn;
            }
        }
    }
}

// ---------------------------------------------------------------------------
// Kernel 2: one warp = one (b,i) row, all 4 heads INTERLEAVED (ILP).
//   scan A once -> compact idx; fast path (count<=64): register-resident
//   logits, 4 heads' shfl reductions in flight simultaneously, gather with
//   8-way MLP (4 heads x 2 entries per step). Slow path: generic loop.
// grid (N/4, B) = 1024 blocks, 128 threads (4 warps).
// ---------------------------------------------------------------------------
#define NW2 4

__global__ void __launch_bounds__(128) k2_attn(
        const float* __restrict__ A,
        const float* __restrict__ biases,
        float* __restrict__ out) {
    __shared__ unsigned short s_idx[NW2][Nn];   // 4 KB
    __shared__ float          s_w[NW2][Nn];     // 8 KB (fast: [h*64+e], slow: [e])

    const int tid  = threadIdx.x;
    const int lane = tid & 31;
    const int wid  = tid >> 5;
    const int b = blockIdx.y;
    const int i = blockIdx.x * NW2 + wid;

    const unsigned ltmask = (1u << lane) - 1u;
    const float* Arow = A + ((size_t)(b * Nn) + i) * Nn;

    // ---- scan + ballot-compact indices (once, shared by all heads) ----
    int count = 0;
    #pragma unroll
    for (int k = 0; k < 16; ++k) {
        const int j = lane + (k << 5);
        bool p = (__ldcs(Arow + j) != 0.f);
        unsigned bal = __ballot_sync(0xffffffffu, p);
        if (p) s_idx[wid][count + __popc(bal & ltmask)] = (unsigned short)j;
        count += __popc(bal);
    }
    __syncwarp();

    const size_t bh0 = (size_t)b * Hh;

    if (count <= 64) {
        // ---------------- fast path ----------------
        const bool v0 = lane < count, v1 = lane + 32 < count;
        const int j0 = v0 ? (int)s_idx[wid][lane]      : 0;
        const int j1 = v1 ? (int)s_idx[wid][lane + 32] : 0;

        float l0[Hh], l1[Hh];
        #pragma unroll
        for (int h = 0; h < Hh; ++h) {
            const float* an_h = g_an + (bh0 + h) * Nn;
            const float a_si = __ldg(g_as + (bh0 + h) * Nn + i);
            float x0 = a_si + __ldg(an_h + j0);
            float x1 = a_si + __ldg(an_h + j1);
            x0 = x0 > 0.f ? x0 : 0.2f * x0;
            x1 = x1 > 0.f ? x1 : 0.2f * x1;
            l0[h] = v0 ? x0 : -1e30f;
            l1[h] = v1 ? x1 : -1e30f;
        }
        // 4 interleaved max reductions
        float m[Hh];
        #pragma unroll
        for (int h = 0; h < Hh; ++h) m[h] = fmaxf(l0[h], l1[h]);
        #pragma unroll
        for (int o = 16; o; o >>= 1)
            #pragma unroll
            for (int h = 0; h < Hh; ++h)
                m[h] = fmaxf(m[h], __shfl_xor_sync(0xffffffffu, m[h], o));
        // exp + 4 interleaved sum reductions
        float s[Hh];
        #pragma unroll
        for (int h = 0; h < Hh; ++h) {
            float w0 = v0 ? __expf(l0[h] - m[h]) : 0.f;
            float w1 = v1 ? __expf(l1[h] - m[h]) : 0.f;
            s_w[wid][h * 64 + lane]      = w0;
            s_w[wid][h * 64 + 32 + lane] = w1;
            s[h] = w0 + w1;
        }
        #pragma unroll
        for (int o = 16; o; o >>= 1)
            #pragma unroll
            for (int h = 0; h < Hh; ++h)
                s[h] += __shfl_xor_sync(0xffffffffu, s[h], o);
        float inv[Hh];
        #pragma unroll
        for (int h = 0; h < Hh; ++h) inv[h] = 1.f / s[h];
        __syncwarp();

        // gather: 4 heads x 2 entries per step -> 8 independent LDGs (MLP=8)
        float2 acc[Hh];
        #pragma unroll
        for (int h = 0; h < Hh; ++h) acc[h] = make_float2(0.f, 0.f);
        const float* fbase = g_feats + bh0 * Nn * Cc;

        int e = 0;
        for (; e + 2 <= count; e += 2) {
            const int ja = s_idx[wid][e], jb = s_idx[wid][e + 1];
            #pragma unroll
            for (int h = 0; h < Hh; ++h) {
                const float* fh = fbase + (size_t)h * Nn * Cc;
                float wa = s_w[wid][h * 64 + e];
                float wb = s_w[wid][h * 64 + e + 1];
                float2 fa = __ldg(reinterpret_cast<const float2*>(fh + (size_t)ja * Cc) + lane);
                float2 fb = __ldg(reinterpret_cast<const float2*>(fh + (size_t)jb * Cc) + lane);
                acc[h].x += wa * fa.x + wb * fb.x;
                acc[h].y += wa * fa.y + wb * fb.y;
            }
        }
        if (e < count) {
            const int ja = s_idx[wid][e];
            #pragma unroll
            for (int h = 0; h < Hh; ++h) {
                const float* fh = fbase + (size_t)h * Nn * Cc;
                float wa = s_w[wid][h * 64 + e];
                float2 fa = __ldg(reinterpret_cast<const float2*>(fh + (size_t)ja * Cc) + lane);
                acc[h].x += wa * fa.x;
                acc[h].y += wa * fa.y;
            }
        }

        #pragma unroll
        for (int h = 0; h < Hh; ++h) {
            float2 bsv = reinterpret_cast<const float2*>(biases + h * Cc)[lane];
            float2 o;
            o.x = fmaxf(acc[h].x * inv[h] + bsv.x, 0.f);
            o.y = fmaxf(acc[h].y * inv[h] + bsv.y, 0.f);
            reinterpret_cast<float2*>(
                out + ((size_t)(b * Nn) + i) * OUTW + Hh * Cc + h * Cc)[lane] = o;
        }
    } else {
        // ---------------- slow path (generic, rare) ----------------
        #pragma unroll 1
        for (int h = 0; h < Hh; ++h) {
            const size_t bh = bh0 + h;
            const float* an_h = g_an + bh * Nn;
            const float* feats_h = g_feats + bh * Nn * Cc;
            const float a_si = __ldg(g_as + bh * Nn + i);

            float m = -1e30f;
            for (int e = lane; e < count; e += 32) {
                float l = a_si + __ldg(an_h + s_idx[wid][e]);
                l = l > 0.f ? l : 0.2f * l;
                s_w[wid][e] = l;
                m = fmaxf(m, l);
            }
            #pragma unroll
            for (int o = 16; o; o >>= 1) m = fmaxf(m, __shfl_xor_sync(0xffffffffu, m, o));
            __syncwarp();

            float s = 0.f;
            for (int e = lane; e < count; e += 32) {
                float w = __expf(s_w[wid][e] - m);
                s_w[wid][e] = w;
                s += w;
            }
            #pragma unroll
            for (int o = 16; o; o >>= 1) s += __shfl_xor_sync(0xffffffffu, s, o);
            const float inv = 1.f / s;
            __syncwarp();

            float2 acc = make_float2(0.f, 0.f);
            for (int e = 0; e < count; ++e) {
                int jj = s_idx[wid][e];
                float ww = s_w[wid][e];
                float2 f = __ldg(reinterpret_cast<const float2*>(feats_h + (size_t)jj * Cc) + lane);
                acc.x += ww * f.x; acc.y += ww * f.y;
            }
            __syncwarp();

            float2 bsv = reinterpret_cast<const float2*>(biases + h * Cc)[lane];
            float2 o;
            o.x = fmaxf(acc.x * inv + bsv.x, 0.f);
            o.y = fmaxf(acc.y * inv + bsv.y, 0.f);
            reinterpret_cast<float2*>(
                out + ((size_t)(b * Nn) + i) * OUTW + Hh * Cc + h * Cc)[lane] = o;
        }
    }
}

// ---------------------------------------------------------------------------
extern "C" void kernel_launch(void* const* d_in, const int* in_sizes, int n_in,
                              void* d_out, int out_size) {
    (void)in_sizes; (void)n_in; (void)out_size;
    const float* X          = (const float*)d_in[0];
    const float* A          = (const float*)d_in[1];
    const float* kernels    = (const float*)d_in[2];
    const float* biases     = (const float*)d_in[3];
    const float* attn_self  = (const float*)d_in[4];
    const float* attn_neigh = (const float*)d_in[5];
    float* out = (float*)d_out;

    const int smem1 = (Ff * Cc + 64 * 132) * 4;   // 66560 B
    cudaFuncSetAttribute(k1_proj, cudaFuncAttributeMaxDynamicSharedMemorySize, smem1);

    k1_proj<<<dim3(Nn / 64, Hh, Bb), 256, smem1>>>(X, kernels, attn_self, attn_neigh, out);
    k2_attn<<<dim3(Nn / NW2, Bb), 128>>>(A, biases, out);
}